// round 15
// baseline (speedup 1.0000x reference)
#include <cuda_runtime.h>
#include <cuda_fp16.h>
#include <cstdint>

#define TT        10
#define NB        32
#define THREADS   512
#define NCTA      (65536 / NB)       // 2048

// smem layout (bytes)
#define BUFS      32768              // one hi-plane buffer = {XRH, XIH} x 16KB
#define XRH_R     0
#define XIH_R     16384
#define XF32R     65536              // exact fp32 state, scol layout, warp-owned (32KB)
#define XF32I     98304
#define AYR_OFF   131072             // Ay fp32 (32KB each)
#define AYI_OFF   163840
#define YRL_OFF   131072             // pass-0 y-lo planes alias the Ay region
#define YIL_OFF   147456
#define SMEM_TOTAL 196608            // 192KB

// Gauss-stacked weights, MMA fragment order:
// uint4 index ((chunk16*48 + gmt)*32 + lane); gmt [0,48): m 0-255 Br, 256-511 Br+Bi, 512-767 Bi-Br
__device__ __half g_WBH[196608];   // 384KB (16 chunks x 48 mtiles)
__device__ __half g_WBL[196608];
__device__ __half g_WAH[98304];    // 192KB (8 chunks x 48 mtiles)
__device__ __half g_WAL[98304];

// ---------------- PTX helpers ----------------
static __device__ __forceinline__ uint32_t smem_u32(const void* p) {
    uint32_t a;
    asm("{ .reg .u64 t; cvta.to.shared.u64 t, %1; cvt.u32.u64 %0, t; }" : "=r"(a) : "l"(p));
    return a;
}
static __device__ __forceinline__ void ldmB4(uint32_t* r, uint32_t addr) {
    asm volatile("ldmatrix.sync.aligned.m8n8.x4.trans.shared.b16 {%0,%1,%2,%3}, [%4];"
                 : "=r"(r[0]), "=r"(r[1]), "=r"(r[2]), "=r"(r[3]) : "r"(addr));
}
static __device__ __forceinline__ void mma16816(float* d, const uint32_t* a, const uint32_t* b) {
    asm volatile("mma.sync.aligned.m16n8k16.row.col.f32.f16.f16.f32 "
                 "{%0,%1,%2,%3}, {%4,%5,%6,%7}, {%8,%9}, {%0,%1,%2,%3};"
                 : "+f"(d[0]), "+f"(d[1]), "+f"(d[2]), "+f"(d[3])
                 : "r"(a[0]), "r"(a[1]), "r"(a[2]), "r"(a[3]), "r"(b[0]), "r"(b[1]));
}
static __device__ __forceinline__ uint32_t hadd2u(uint32_t a, uint32_t b) {
    __half2 r = __hadd2(*(__half2*)&a, *(__half2*)&b);
    return *(uint32_t*)&r;
}
// Swizzle for 64B rows (hi planes)
static __device__ __host__ __forceinline__ uint32_t swz64(int row, int colbyte) {
    return (uint32_t)(row * 64 + (colbyte ^ ((row & 6) << 3)));
}
// fp32 scratch column shift: word index within a 32-word row
static __device__ __forceinline__ uint32_t scol(int m, int n0) {
    return (uint32_t)((n0 + ((m & 3) << 3)) & 31);
}

// ---------------- prep: Gauss-stacked W', fp16 hi/lo fragment order ----------------
__global__ void prep_kernel(const float* __restrict__ A, const float* __restrict__ B) {
    const int NBEL = 768 * 256, NAEL = 768 * 128;
    for (int i = blockIdx.x * blockDim.x + threadIdx.x; i < NBEL + NAEL;
         i += gridDim.x * blockDim.x) {
        int R, k;
        float w;
        __half *dH, *dL;
        if (i < NBEL) {
            R = i >> 8; k = i & 255;
            const int grp = R >> 8, m = R & 255;
            const float br = B[m * 256 + k], bi = B[65536 + m * 256 + k];
            w = (grp == 0) ? br : ((grp == 1) ? br + bi : bi - br);
            dH = g_WBH; dL = g_WBL;
        } else {
            const int j = i - NBEL;
            R = j >> 7; k = j & 127;
            const int grp = R >> 8, m = R & 255;
            const float ar = A[m * 128 + k], ai = A[32768 + m * 128 + k];
            w = (grp == 0) ? ar : ((grp == 1) ? ar + ai : ai - ar);
            dH = g_WAH; dL = g_WAL;
        }
        const int gmt = R >> 4, row = R & 15, chunk = k >> 4, kk = k & 15;
        const int rr = (row >> 3) | ((kk >> 3) << 1);
        const int t = (kk & 7) >> 1, pos = kk & 1;
        const int lane = (row & 7) * 4 + t;
        const int dest = ((chunk * 48 + gmt) * 32 + lane) * 8 + rr * 2 + pos;
        __half hi = __float2half_rn(w);
        dH[dest] = hi;
        dL[dest] = __float2half_rn(w - __half2float(hi));
    }
}

// load 6 A fragments (hi k1,k2,k3; lo k1,k2,k3) for K16 chunk c
static __device__ __forceinline__ void ldA6(uint4* A, const uint4* gH, const uint4* gL,
                                            int i1, int i2, int i3, int c) {
    const int o = c * (48 * 32);
    A[0] = __ldg(gH + i1 + o); A[1] = __ldg(gH + i2 + o); A[2] = __ldg(gH + i3 + o);
    A[3] = __ldg(gL + i1 + o); A[4] = __ldg(gL + i2 + o); A[5] = __ldg(gL + i3 + o);
}

// ---------------- warp-local sweep: k1,k2,k3 all for this warp's m-range ----------------
// acc[12][4]: [0..3]=k1 (nt 0..3), [4..7]=k2, [8..11]=k3
static __device__ __forceinline__ void sweep(
    const char* smc, uint32_t rbase, const __half* gHh, const __half* gLh, int NC, bool term3,
    float (*acc)[4], int i1, int i2, int i3, int lane, uint4* A0, uint4* A1)
{
    const uint4* gH = (const uint4*)gHh;
    const uint4* gL = (const uint4*)gLh;
    const uint32_t smb = smem_u32(smc);
    const uint32_t smr = smb + rbase;
    const uint32_t bxor = (uint32_t)((lane & 6) << 3);
    const uint32_t brow = ((uint32_t)(lane & 7) + ((uint32_t)((lane >> 3) & 1)) * 8) * 64;
    const uint32_t bcol0 = (((uint32_t)(lane >> 4) * 16)) ^ bxor;
    const uint32_t bcol1 = (32u + (uint32_t)(lane >> 4) * 16) ^ bxor;

#pragma unroll
    for (int i = 0; i < 12; ++i)
#pragma unroll
        for (int j = 0; j < 4; ++j) acc[i][j] = 0.0f;

#pragma unroll 1
    for (int c = 0; c < NC; c += 2) {
#pragma unroll
        for (int half = 0; half < 2; ++half) {
            const uint4* Ar = half ? A1 : A0;
            const uint32_t co = (uint32_t)(c + half) << 10;
            uint32_t br[8], bi[8];
            ldmB4(br,     smr + XRH_R + co + brow + bcol0);
            ldmB4(br + 4, smr + XRH_R + co + brow + bcol1);
            ldmB4(bi,     smr + XIH_R + co + brow + bcol0);
            ldmB4(bi + 4, smr + XIH_R + co + brow + bcol1);
            // k3 = (Bi-Br)*xr  (br live)
#pragma unroll
            for (int nt = 0; nt < 4; ++nt)
                mma16816(acc[8 + nt], (const uint32_t*)&Ar[2], &br[nt * 2]);
#pragma unroll
            for (int nt = 0; nt < 4; ++nt)
                mma16816(acc[8 + nt], (const uint32_t*)&Ar[5], &br[nt * 2]);
            // k2 = (Br+Bi)*xi
#pragma unroll
            for (int nt = 0; nt < 4; ++nt)
                mma16816(acc[4 + nt], (const uint32_t*)&Ar[1], &bi[nt * 2]);
#pragma unroll
            for (int nt = 0; nt < 4; ++nt)
                mma16816(acc[4 + nt], (const uint32_t*)&Ar[4], &bi[nt * 2]);
            // xs = xr + xi in-place, then k1 = Br*xs
#pragma unroll
            for (int j = 0; j < 8; ++j) br[j] = hadd2u(br[j], bi[j]);
#pragma unroll
            for (int nt = 0; nt < 4; ++nt)
                mma16816(acc[nt], (const uint32_t*)&Ar[0], &br[nt * 2]);
#pragma unroll
            for (int nt = 0; nt < 4; ++nt)
                mma16816(acc[nt], (const uint32_t*)&Ar[3], &br[nt * 2]);
            if (term3) {
                // pass-0 only: Wh * y_lo for all three terms (y-lo aliased in Ay region)
                uint32_t brl[8], bil[8];
                ldmB4(brl,     smb + YRL_OFF + co + brow + bcol0);
                ldmB4(brl + 4, smb + YRL_OFF + co + brow + bcol1);
                ldmB4(bil,     smb + YIL_OFF + co + brow + bcol0);
                ldmB4(bil + 4, smb + YIL_OFF + co + brow + bcol1);
#pragma unroll
                for (int nt = 0; nt < 4; ++nt)
                    mma16816(acc[8 + nt], (const uint32_t*)&Ar[2], &brl[nt * 2]);
#pragma unroll
                for (int nt = 0; nt < 4; ++nt)
                    mma16816(acc[4 + nt], (const uint32_t*)&Ar[1], &bil[nt * 2]);
#pragma unroll
                for (int j = 0; j < 8; ++j) brl[j] = hadd2u(brl[j], bil[j]);
#pragma unroll
                for (int nt = 0; nt < 4; ++nt)
                    mma16816(acc[nt], (const uint32_t*)&Ar[0], &brl[nt * 2]);
            }
            // prefetch this buffer's next chunk (within pass)
            const int pf = c + half + 2;
            if (pf < NC) ldA6(half ? A1 : A0, gH, gL, i1, i2, i3, pf);
        }
    }
}

// ---------------- main fused kernel ----------------
__global__ __launch_bounds__(THREADS, 1)
void lista_main(const float* __restrict__ y,
                const float* __restrict__ etas,
                const float* __restrict__ gammas,
                float* __restrict__ out) {
    extern __shared__ char smc[];
    const int tid = threadIdx.x, lane = tid & 31, wid = tid >> 5;
    const long b0 = (long)blockIdx.x * NB;

    // stage y: hi planes into buffer 0, lo planes into the Ay alias
    const float2* y2 = (const float2*)y;
    for (int idx = tid; idx < NB * 128; idx += THREADS) {
        const int n = idx >> 7, q = idx & 127;
        const float2 v = y2[(b0 + n) * 128 + q];
        const uint32_t off = swz64(q, n * 2);
        __half hr = __float2half_rn(v.x);
        __half hi = __float2half_rn(v.y);
        *(__half*)(smc + XRH_R + off) = hr;
        *(__half*)(smc + YRL_OFF + off) = __float2half_rn(v.x - __half2float(hr));
        *(__half*)(smc + XIH_R + off) = hi;
        *(__half*)(smc + YIL_OFF + off) = __float2half_rn(v.y - __half2float(hi));
    }
    __syncthreads();

    // lane geometry
    const int eg = lane >> 2, ec = lane & 3;
    // warp-local Gauss mtiles: k1 = gmt wid, k2 = gmt 16+wid, k3 = gmt 32+wid
    const int i1 = wid * 32 + lane;
    const int i2 = (16 + wid) * 32 + lane;
    const int i3 = (32 + wid) * 32 + lane;

    float acc[12][4];
    uint4 A0[6], A1[6];
    ldA6(A0, (const uint4*)g_WAH, (const uint4*)g_WAL, i1, i2, i3, 0);
    ldA6(A1, (const uint4*)g_WAH, (const uint4*)g_WAL, i1, i2, i3, 1);

#pragma unroll 1
    for (int t = 0; t <= TT; ++t) {
        const bool t3 = (t == 0);
        const __half* WH = t ? g_WBH : g_WAH;
        const __half* WL = t ? g_WBL : g_WAL;
        const int NC = t ? 16 : 8;
        const uint32_t rb = (uint32_t)(t & 1) * BUFS;        // read buffer (hi planes)
        const uint32_t wb = (uint32_t)(1 - (t & 1)) * BUFS;  // write buffer

        sweep(smc, rb, WH, WL, NC, t3, acc, i1, i2, i3, lane, A0, A1);

        if (t == 0) __syncthreads();   // y-lo alias: all sweep reads done before Ay store

        // cross-pass A prefetch: hide next pass's cold-start LDGs under the epilogue
        if (t < TT) {
            ldA6(A0, (const uint4*)g_WBH, (const uint4*)g_WBL, i1, i2, i3, 0);
            ldA6(A1, (const uint4*)g_WBH, (const uint4*)g_WBL, i1, i2, i3, 1);
        }

        // warp-local combine + LISTA update (fp32 state; hi planes to inactive buffer)
        const float g = gammas[t], e = etas[t];
#pragma unroll
        for (int nt = 0; nt < 4; ++nt)
#pragma unroll
            for (int rg = 0; rg < 2; ++rg) {
                const int m = 16 * wid + eg + rg * 8;
                const int n0 = nt * 8 + ec * 2;
                const uint32_t w = (uint32_t)m * 32 + scol(m, n0);
                const float k1a = acc[nt][rg * 2 + 0],     k1b = acc[nt][rg * 2 + 1];
                const float k2a = acc[4 + nt][rg * 2 + 0], k2b = acc[4 + nt][rg * 2 + 1];
                const float k3a = acc[8 + nt][rg * 2 + 0], k3b = acc[8 + nt][rg * 2 + 1];
                const float bre0 = k1a - k2a, bre1 = k1b - k2b;
                const float bim0 = k1a + k3a, bim1 = k1b + k3b;
                float vre0, vre1, vim0, vim1;
                if (t == 0) {
                    *(float2*)(smc + AYR_OFF + w * 4) = make_float2(bre0, bre1);
                    *(float2*)(smc + AYI_OFF + w * 4) = make_float2(bim0, bim1);
                    vre0 = g * bre0; vre1 = g * bre1;
                    vim0 = g * bim0; vim1 = g * bim1;
                } else {
                    const float2 ar = *(const float2*)(smc + AYR_OFF + w * 4);
                    const float2 ai = *(const float2*)(smc + AYI_OFF + w * 4);
                    const float2 xr = *(const float2*)(smc + XF32R + w * 4);
                    const float2 xi = *(const float2*)(smc + XF32I + w * 4);
                    vre0 = fmaf(g, ar.x - bre0, xr.x);
                    vre1 = fmaf(g, ar.y - bre1, xr.y);
                    vim0 = fmaf(g, ai.x - bim0, xi.x);
                    vim1 = fmaf(g, ai.y - bim1, xi.y);
                }
                const float xr0 = copysignf(fmaxf(fabsf(vre0) - e, 0.0f), vre0);
                const float xr1 = copysignf(fmaxf(fabsf(vre1) - e, 0.0f), vre1);
                const float xi0 = copysignf(fmaxf(fabsf(vim0) - e, 0.0f), vim0);
                const float xi1 = copysignf(fmaxf(fabsf(vim1) - e, 0.0f), vim1);
                // exact fp32 state (warp-owned)
                *(float2*)(smc + XF32R + w * 4) = make_float2(xr0, xr1);
                *(float2*)(smc + XF32I + w * 4) = make_float2(xi0, xi1);
                // hi planes for next sweep's MMA operands (skip on last pass)
                if (t < TT) {
                    const uint32_t off = swz64(m, n0 * 2);
                    *(__half2*)(smc + wb + XRH_R + off) =
                        __halves2half2(__float2half_rn(xr0), __float2half_rn(xr1));
                    *(__half2*)(smc + wb + XIH_R + off) =
                        __halves2half2(__float2half_rn(xi0), __float2half_rn(xi1));
                }
            }
        __syncthreads();   // one barrier per pass
    }

    // output from exact fp32 state: out[b][m][c]
    for (int idx = tid; idx < NB * 512; idx += THREADS) {
        const int n = idx >> 9, i = idx & 511, m = i >> 1, cc = i & 1;
        const uint32_t base = cc ? XF32I : XF32R;
        const uint32_t w = (uint32_t)m * 32 + scol(m, n);
        out[(b0 + n) * 512 + i] = *(const float*)(smc + base + w * 4);
    }
}

extern "C" void kernel_launch(void* const* d_in, const int* in_sizes, int n_in,
                              void* d_out, int out_size) {
    const float* y      = (const float*)d_in[0];
    const float* A      = (const float*)d_in[1];
    const float* B      = (const float*)d_in[2];
    const float* etas   = (const float*)d_in[3];
    const float* gammas = (const float*)d_in[4];
    float* out = (float*)d_out;

    prep_kernel<<<576, 512>>>(A, B);

    cudaFuncSetAttribute(lista_main, cudaFuncAttributeMaxDynamicSharedMemorySize, SMEM_TOTAL);
    lista_main<<<NCTA, THREADS, SMEM_TOTAL>>>(y, etas, gammas, out);
}

// round 16
// speedup vs baseline: 1.1435x; 1.1435x over previous
#include <cuda_runtime.h>
#include <cuda_fp16.h>
#include <cstdint>

#define TT        10
#define NB        32
#define THREADS   512
#define NCTA      (65536 / NB)       // 2048

// smem layout (bytes): two x-state buffers, each 64KB = {XRH,XIH,XRL,XIL} x 16KB
#define BUFS      65536
#define XRH_R     0
#define XIH_R     16384
#define XRL_R     32768
#define XIL_R     49152
#define AYR_OFF   131072             // Ay fp32 (scol-shifted), 32KB each
#define AYI_OFF   163840
#define SMEM_TOTAL 196608            // 192KB

// Gauss-stacked weights, MMA fragment order:
// uint4 index ((chunk16*48 + gmt)*32 + lane); gmt [0,48): m 0-255 Br, 256-511 Br+Bi, 512-767 Bi-Br
__device__ __half g_WBH[196608];   // 384KB (16 chunks x 48 mtiles)
__device__ __half g_WBL[196608];
__device__ __half g_WAH[98304];    // 192KB (8 chunks x 48 mtiles)
__device__ __half g_WAL[98304];

// ---------------- PTX helpers ----------------
static __device__ __forceinline__ uint32_t smem_u32(const void* p) {
    uint32_t a;
    asm("{ .reg .u64 t; cvta.to.shared.u64 t, %1; cvt.u32.u64 %0, t; }" : "=r"(a) : "l"(p));
    return a;
}
static __device__ __forceinline__ void ldmB4(uint32_t* r, uint32_t addr) {
    asm volatile("ldmatrix.sync.aligned.m8n8.x4.trans.shared.b16 {%0,%1,%2,%3}, [%4];"
                 : "=r"(r[0]), "=r"(r[1]), "=r"(r[2]), "=r"(r[3]) : "r"(addr));
}
static __device__ __forceinline__ void mma16816(float* d, const uint32_t* a, const uint32_t* b) {
    asm volatile("mma.sync.aligned.m16n8k16.row.col.f32.f16.f16.f32 "
                 "{%0,%1,%2,%3}, {%4,%5,%6,%7}, {%8,%9}, {%0,%1,%2,%3};"
                 : "+f"(d[0]), "+f"(d[1]), "+f"(d[2]), "+f"(d[3])
                 : "r"(a[0]), "r"(a[1]), "r"(a[2]), "r"(a[3]), "r"(b[0]), "r"(b[1]));
}
static __device__ __forceinline__ uint32_t hadd2u(uint32_t a, uint32_t b) {
    __half2 r = __hadd2(*(__half2*)&a, *(__half2*)&b);
    return *(uint32_t*)&r;
}
// Swizzle for 64B rows (hi/lo planes)
static __device__ __host__ __forceinline__ uint32_t swz64(int row, int colbyte) {
    return (uint32_t)(row * 64 + (colbyte ^ ((row & 6) << 3)));
}
// fp32 scratch column shift: word index within a 32-word row
static __device__ __forceinline__ uint32_t scol(int m, int n0) {
    return (uint32_t)((n0 + ((m & 3) << 3)) & 31);
}

// ---------------- prep: Gauss-stacked W', fp16 hi/lo fragment order ----------------
__global__ void prep_kernel(const float* __restrict__ A, const float* __restrict__ B) {
    const int NBEL = 768 * 256, NAEL = 768 * 128;
    for (int i = blockIdx.x * blockDim.x + threadIdx.x; i < NBEL + NAEL;
         i += gridDim.x * blockDim.x) {
        int R, k;
        float w;
        __half *dH, *dL;
        if (i < NBEL) {
            R = i >> 8; k = i & 255;
            const int grp = R >> 8, m = R & 255;
            const float br = B[m * 256 + k], bi = B[65536 + m * 256 + k];
            w = (grp == 0) ? br : ((grp == 1) ? br + bi : bi - br);
            dH = g_WBH; dL = g_WBL;
        } else {
            const int j = i - NBEL;
            R = j >> 7; k = j & 127;
            const int grp = R >> 8, m = R & 255;
            const float ar = A[m * 128 + k], ai = A[32768 + m * 128 + k];
            w = (grp == 0) ? ar : ((grp == 1) ? ar + ai : ai - ar);
            dH = g_WAH; dL = g_WAL;
        }
        const int gmt = R >> 4, row = R & 15, chunk = k >> 4, kk = k & 15;
        const int rr = (row >> 3) | ((kk >> 3) << 1);
        const int t = (kk & 7) >> 1, pos = kk & 1;
        const int lane = (row & 7) * 4 + t;
        const int dest = ((chunk * 48 + gmt) * 32 + lane) * 8 + rr * 2 + pos;
        __half hi = __float2half_rn(w);
        dH[dest] = hi;
        dL[dest] = __float2half_rn(w - __half2float(hi));
    }
}

// load A fragments for K16 chunk c: full=6 (hi k1,k2,k3 + lo k1,k2,k3), else 4 (hi x3 + lo k1)
static __device__ __forceinline__ void ldA(uint4* A, const uint4* gH, const uint4* gL,
                                           int i1, int i2, int i3, int c, bool full) {
    const int o = c * (48 * 32);
    A[0] = __ldg(gH + i1 + o); A[1] = __ldg(gH + i2 + o); A[2] = __ldg(gH + i3 + o);
    A[3] = __ldg(gL + i1 + o);
    if (full) { A[4] = __ldg(gL + i2 + o); A[5] = __ldg(gL + i3 + o); }
}

// ---------------- warp-local sweep: k1,k2,k3 all for this warp's m-range ----------------
// acc[12][4]: [0..3]=k1 (nt 0..3), [4..7]=k2, [8..11]=k3
// t>=1: k1 gets Wh+Wl (exact W), k2/k3 get Wh only (Wl dropped: 2^-12 W-noise, accepted)
static __device__ __forceinline__ void sweep(
    const char* smc, uint32_t rbase, const __half* gHh, const __half* gLh, int NC, bool full,
    float (*acc)[4], int i1, int i2, int i3, int lane, uint4* A0, uint4* A1)
{
    const uint4* gH = (const uint4*)gHh;
    const uint4* gL = (const uint4*)gLh;
    const uint32_t smb = smem_u32(smc) + rbase;
    const uint32_t bxor = (uint32_t)((lane & 6) << 3);
    const uint32_t brow = ((uint32_t)(lane & 7) + ((uint32_t)((lane >> 3) & 1)) * 8) * 64;
    const uint32_t bcol0 = (((uint32_t)(lane >> 4) * 16)) ^ bxor;
    const uint32_t bcol1 = (32u + (uint32_t)(lane >> 4) * 16) ^ bxor;

#pragma unroll
    for (int i = 0; i < 12; ++i)
#pragma unroll
        for (int j = 0; j < 4; ++j) acc[i][j] = 0.0f;

#pragma unroll 1
    for (int c = 0; c < NC; c += 2) {
#pragma unroll
        for (int half = 0; half < 2; ++half) {
            const uint4* Ar = half ? A1 : A0;
            const uint32_t co = (uint32_t)(c + half) << 10;
            uint32_t br[8], bi[8];
            ldmB4(br,     smb + XRH_R + co + brow + bcol0);
            ldmB4(br + 4, smb + XRH_R + co + brow + bcol1);
            ldmB4(bi,     smb + XIH_R + co + brow + bcol0);
            ldmB4(bi + 4, smb + XIH_R + co + brow + bcol1);
            // k3 = (Bi-Br)h * xr  (br live)
#pragma unroll
            for (int nt = 0; nt < 4; ++nt)
                mma16816(acc[8 + nt], (const uint32_t*)&Ar[2], &br[nt * 2]);
            if (full) {
#pragma unroll
                for (int nt = 0; nt < 4; ++nt)
                    mma16816(acc[8 + nt], (const uint32_t*)&Ar[5], &br[nt * 2]);
            }
            // k2 = (Br+Bi)h * xi
#pragma unroll
            for (int nt = 0; nt < 4; ++nt)
                mma16816(acc[4 + nt], (const uint32_t*)&Ar[1], &bi[nt * 2]);
            if (full) {
#pragma unroll
                for (int nt = 0; nt < 4; ++nt)
                    mma16816(acc[4 + nt], (const uint32_t*)&Ar[4], &bi[nt * 2]);
            }
            // xs = xr + xi in-place, then k1 = (Br_h + Br_l) * xs  (exact W on k1)
#pragma unroll
            for (int j = 0; j < 8; ++j) br[j] = hadd2u(br[j], bi[j]);
#pragma unroll
            for (int nt = 0; nt < 4; ++nt)
                mma16816(acc[nt], (const uint32_t*)&Ar[0], &br[nt * 2]);
#pragma unroll
            for (int nt = 0; nt < 4; ++nt)
                mma16816(acc[nt], (const uint32_t*)&Ar[3], &br[nt * 2]);
            if (full) {
                // pass-0 only: Wh * x_lo for all three terms (full 3-term Ay)
                uint32_t brl[8], bil[8];
                ldmB4(brl,     smb + XRL_R + co + brow + bcol0);
                ldmB4(brl + 4, smb + XRL_R + co + brow + bcol1);
                ldmB4(bil,     smb + XIL_R + co + brow + bcol0);
                ldmB4(bil + 4, smb + XIL_R + co + brow + bcol1);
#pragma unroll
                for (int nt = 0; nt < 4; ++nt)
                    mma16816(acc[8 + nt], (const uint32_t*)&Ar[2], &brl[nt * 2]);
#pragma unroll
                for (int nt = 0; nt < 4; ++nt)
                    mma16816(acc[4 + nt], (const uint32_t*)&Ar[1], &bil[nt * 2]);
#pragma unroll
                for (int j = 0; j < 8; ++j) brl[j] = hadd2u(brl[j], bil[j]);
#pragma unroll
                for (int nt = 0; nt < 4; ++nt)
                    mma16816(acc[nt], (const uint32_t*)&Ar[0], &brl[nt * 2]);
            }
            // prefetch this buffer's next chunk (within pass)
            const int pf = c + half + 2;
            if (pf < NC) ldA(half ? A1 : A0, gH, gL, i1, i2, i3, pf, full);
        }
    }
}

// ---------------- main fused kernel ----------------
__global__ __launch_bounds__(THREADS, 1)
void lista_main(const float* __restrict__ y,
                const float* __restrict__ etas,
                const float* __restrict__ gammas,
                float* __restrict__ out) {
    extern __shared__ char smc[];
    const int tid = threadIdx.x, lane = tid & 31, wid = tid >> 5;
    const long b0 = (long)blockIdx.x * NB;

    // stage y into buffer 0: yr -> XRH/XRL, yi -> XIH/XIL
    const float2* y2 = (const float2*)y;
    for (int idx = tid; idx < NB * 128; idx += THREADS) {
        const int n = idx >> 7, q = idx & 127;
        const float2 v = y2[(b0 + n) * 128 + q];
        const uint32_t off = swz64(q, n * 2);
        __half hr = __float2half_rn(v.x);
        __half hi = __float2half_rn(v.y);
        *(__half*)(smc + XRH_R + off) = hr;
        *(__half*)(smc + XRL_R + off) = __float2half_rn(v.x - __half2float(hr));
        *(__half*)(smc + XIH_R + off) = hi;
        *(__half*)(smc + XIL_R + off) = __float2half_rn(v.y - __half2float(hi));
    }
    __syncthreads();

    // lane geometry
    const int eg = lane >> 2, ec = lane & 3;
    // warp-local Gauss mtiles: k1 = gmt wid, k2 = gmt 16+wid, k3 = gmt 32+wid
    const int i1 = wid * 32 + lane;
    const int i2 = (16 + wid) * 32 + lane;
    const int i3 = (32 + wid) * 32 + lane;

    float acc[12][4];
    uint4 A0[6], A1[6];
    ldA(A0, (const uint4*)g_WAH, (const uint4*)g_WAL, i1, i2, i3, 0, true);
    ldA(A1, (const uint4*)g_WAH, (const uint4*)g_WAL, i1, i2, i3, 1, true);

#pragma unroll 1
    for (int t = 0; t <= TT; ++t) {
        const bool full = (t == 0);
        const __half* WH = t ? g_WBH : g_WAH;
        const __half* WL = t ? g_WBL : g_WAL;
        const int NC = t ? 16 : 8;
        const uint32_t rb = (uint32_t)(t & 1) * BUFS;        // read buffer
        const uint32_t wb = (uint32_t)(1 - (t & 1)) * BUFS;  // write buffer

        sweep(smc, rb, WH, WL, NC, full, acc, i1, i2, i3, lane, A0, A1);

        // cross-pass A prefetch: hide next pass's cold-start LDGs under the epilogue
        if (t < TT) {
            ldA(A0, (const uint4*)g_WBH, (const uint4*)g_WBL, i1, i2, i3, 0, false);
            ldA(A1, (const uint4*)g_WBH, (const uint4*)g_WBL, i1, i2, i3, 1, false);
        }

        // warp-local combine + LISTA update (no barrier before: write buffer is inactive)
        const float g = gammas[t], e = etas[t];
#pragma unroll
        for (int nt = 0; nt < 4; ++nt)
#pragma unroll
            for (int rg = 0; rg < 2; ++rg) {
                const int m = 16 * wid + eg + rg * 8;
                const int n0 = nt * 8 + ec * 2;
                const uint32_t w = (uint32_t)m * 32 + scol(m, n0);
                const float k1a = acc[nt][rg * 2 + 0],     k1b = acc[nt][rg * 2 + 1];
                const float k2a = acc[4 + nt][rg * 2 + 0], k2b = acc[4 + nt][rg * 2 + 1];
                const float k3a = acc[8 + nt][rg * 2 + 0], k3b = acc[8 + nt][rg * 2 + 1];
                const float bre0 = k1a - k2a, bre1 = k1b - k2b;
                const float bim0 = k1a + k3a, bim1 = k1b + k3b;
                const uint32_t off = swz64(m, n0 * 2);
                float vre0, vre1, vim0, vim1;
                if (t == 0) {
                    *(float2*)(smc + AYR_OFF + w * 4) = make_float2(bre0, bre1);
                    *(float2*)(smc + AYI_OFF + w * 4) = make_float2(bim0, bim1);
                    vre0 = g * bre0; vre1 = g * bre1;
                    vim0 = g * bim0; vim1 = g * bim1;
                } else {
                    const float2 ar = *(const float2*)(smc + AYR_OFF + w * 4);
                    const float2 ai = *(const float2*)(smc + AYI_OFF + w * 4);
                    float2 fr  = __half22float2(*(const __half2*)(smc + rb + XRH_R + off));
                    float2 frl = __half22float2(*(const __half2*)(smc + rb + XRL_R + off));
                    float2 fi  = __half22float2(*(const __half2*)(smc + rb + XIH_R + off));
                    float2 fil = __half22float2(*(const __half2*)(smc + rb + XIL_R + off));
                    vre0 = fmaf(g, ar.x - bre0, fr.x + frl.x);
                    vre1 = fmaf(g, ar.y - bre1, fr.y + frl.y);
                    vim0 = fmaf(g, ai.x - bim0, fi.x + fil.x);
                    vim1 = fmaf(g, ai.y - bim1, fi.y + fil.y);
                }
                const float xr0 = copysignf(fmaxf(fabsf(vre0) - e, 0.0f), vre0);
                const float xr1 = copysignf(fmaxf(fabsf(vre1) - e, 0.0f), vre1);
                const float xi0 = copysignf(fmaxf(fabsf(vim0) - e, 0.0f), vim0);
                const float xi1 = copysignf(fmaxf(fabsf(vim1) - e, 0.0f), vim1);
                __half h0 = __float2half_rn(xr0), h1 = __float2half_rn(xr1);
                *(__half2*)(smc + wb + XRH_R + off) = __halves2half2(h0, h1);
                *(__half2*)(smc + wb + XRL_R + off) = __halves2half2(
                    __float2half_rn(xr0 - __half2float(h0)),
                    __float2half_rn(xr1 - __half2float(h1)));
                __half g0 = __float2half_rn(xi0), g1 = __float2half_rn(xi1);
                *(__half2*)(smc + wb + XIH_R + off) = __halves2half2(g0, g1);
                *(__half2*)(smc + wb + XIL_R + off) = __halves2half2(
                    __float2half_rn(xi0 - __half2float(g0)),
                    __float2half_rn(xi1 - __half2float(g1)));
            }
        __syncthreads();   // one barrier per pass: wb visible before next sweep reads it
    }

    // output: pass TT wrote buffer 1
    const char* xf = smc + BUFS;
    for (int idx = tid; idx < NB * 512; idx += THREADS) {
        const int n = idx >> 9, i = idx & 511, m = i >> 1, cc = i & 1;
        const uint32_t ph = cc ? XIH_R : XRH_R;
        const uint32_t pl = cc ? XIL_R : XRL_R;
        const uint32_t off = swz64(m, n * 2);
        const float v = __half2float(*(const __half*)(xf + ph + off))
                      + __half2float(*(const __half*)(xf + pl + off));
        out[(b0 + n) * 512 + i] = v;
    }
}

extern "C" void kernel_launch(void* const* d_in, const int* in_sizes, int n_in,
                              void* d_out, int out_size) {
    const float* y      = (const float*)d_in[0];
    const float* A      = (const float*)d_in[1];
    const float* B      = (const float*)d_in[2];
    const float* etas   = (const float*)d_in[3];
    const float* gammas = (const float*)d_in[4];
    float* out = (float*)d_out;

    prep_kernel<<<576, 512>>>(A, B);

    cudaFuncSetAttribute(lista_main, cudaFuncAttributeMaxDynamicSharedMemorySize, SMEM_TOTAL);
    lista_main<<<NCTA, THREADS, SMEM_TOTAL>>>(y, etas, gammas, out);
}

// round 17
// speedup vs baseline: 1.2876x; 1.1260x over previous
#include <cuda_runtime.h>
#include <cuda_fp16.h>
#include <cstdint>

#define TT        10
#define NB        32
#define THREADS   512
#define NCTA      (65536 / NB)       // 2048

// smem layout (bytes): two x-state buffers, each 64KB = {XRH,XIH,XRL,XIL} x 16KB
#define BUFS      65536
#define XRH_R     0
#define XIH_R     16384
#define XRL_R     32768
#define XIL_R     49152
#define AYR_OFF   131072             // Ay fp32 (scol-shifted), 32KB each
#define AYI_OFF   163840
#define SMEM_TOTAL 196608            // 192KB

// Gauss-stacked weights, MMA fragment order:
// uint4 index ((chunk16*48 + gmt)*32 + lane); gmt [0,48): m 0-255 Br, 256-511 Br+Bi, 512-767 Bi-Br
__device__ __half g_WBH[196608];   // 384KB (16 chunks x 48 mtiles)
__device__ __half g_WBL[196608];   // (unused by main kernel after R17; kept for prep symmetry)
__device__ __half g_WAH[98304];    // 192KB (8 chunks x 48 mtiles)
__device__ __half g_WAL[98304];

// ---------------- PTX helpers ----------------
static __device__ __forceinline__ uint32_t smem_u32(const void* p) {
    uint32_t a;
    asm("{ .reg .u64 t; cvta.to.shared.u64 t, %1; cvt.u32.u64 %0, t; }" : "=r"(a) : "l"(p));
    return a;
}
static __device__ __forceinline__ void ldmB4(uint32_t* r, uint32_t addr) {
    asm volatile("ldmatrix.sync.aligned.m8n8.x4.trans.shared.b16 {%0,%1,%2,%3}, [%4];"
                 : "=r"(r[0]), "=r"(r[1]), "=r"(r[2]), "=r"(r[3]) : "r"(addr));
}
static __device__ __forceinline__ void mma16816(float* d, const uint32_t* a, const uint32_t* b) {
    asm volatile("mma.sync.aligned.m16n8k16.row.col.f32.f16.f16.f32 "
                 "{%0,%1,%2,%3}, {%4,%5,%6,%7}, {%8,%9}, {%0,%1,%2,%3};"
                 : "+f"(d[0]), "+f"(d[1]), "+f"(d[2]), "+f"(d[3])
                 : "r"(a[0]), "r"(a[1]), "r"(a[2]), "r"(a[3]), "r"(b[0]), "r"(b[1]));
}
static __device__ __forceinline__ uint32_t hadd2u(uint32_t a, uint32_t b) {
    __half2 r = __hadd2(*(__half2*)&a, *(__half2*)&b);
    return *(uint32_t*)&r;
}
// Swizzle for 64B rows (hi/lo planes)
static __device__ __host__ __forceinline__ uint32_t swz64(int row, int colbyte) {
    return (uint32_t)(row * 64 + (colbyte ^ ((row & 6) << 3)));
}
// fp32 scratch column shift: word index within a 32-word row
static __device__ __forceinline__ uint32_t scol(int m, int n0) {
    return (uint32_t)((n0 + ((m & 3) << 3)) & 31);
}

// ---------------- prep: Gauss-stacked W', fp16 hi/lo fragment order ----------------
__global__ void prep_kernel(const float* __restrict__ A, const float* __restrict__ B) {
    const int NBEL = 768 * 256, NAEL = 768 * 128;
    for (int i = blockIdx.x * blockDim.x + threadIdx.x; i < NBEL + NAEL;
         i += gridDim.x * blockDim.x) {
        int R, k;
        float w;
        __half *dH, *dL;
        if (i < NBEL) {
            R = i >> 8; k = i & 255;
            const int grp = R >> 8, m = R & 255;
            const float br = B[m * 256 + k], bi = B[65536 + m * 256 + k];
            w = (grp == 0) ? br : ((grp == 1) ? br + bi : bi - br);
            dH = g_WBH; dL = g_WBL;
        } else {
            const int j = i - NBEL;
            R = j >> 7; k = j & 127;
            const int grp = R >> 8, m = R & 255;
            const float ar = A[m * 128 + k], ai = A[32768 + m * 128 + k];
            w = (grp == 0) ? ar : ((grp == 1) ? ar + ai : ai - ar);
            dH = g_WAH; dL = g_WAL;
        }
        const int gmt = R >> 4, row = R & 15, chunk = k >> 4, kk = k & 15;
        const int rr = (row >> 3) | ((kk >> 3) << 1);
        const int t = (kk & 7) >> 1, pos = kk & 1;
        const int lane = (row & 7) * 4 + t;
        const int dest = ((chunk * 48 + gmt) * 32 + lane) * 8 + rr * 2 + pos;
        __half hi = __float2half_rn(w);
        dH[dest] = hi;
        dL[dest] = __float2half_rn(w - __half2float(hi));
    }
}

// load A fragments for K16 chunk c: full=6 (hi k1,k2,k3 + lo k1,k2,k3), else 3 (hi only)
static __device__ __forceinline__ void ldA(uint4* A, const uint4* gH, const uint4* gL,
                                           int i1, int i2, int i3, int c, bool full) {
    const int o = c * (48 * 32);
    A[0] = __ldg(gH + i1 + o); A[1] = __ldg(gH + i2 + o); A[2] = __ldg(gH + i3 + o);
    if (full) {
        A[3] = __ldg(gL + i1 + o); A[4] = __ldg(gL + i2 + o); A[5] = __ldg(gL + i3 + o);
    }
}

// ---------------- warp-local sweep: k1,k2,k3 all for this warp's m-range ----------------
// acc[12][4]: [0..3]=k1 (nt 0..3), [4..7]=k2, [8..11]=k3
// t>=1: pure Wh operator (12 MMAs/chunk); t=0: full 3-term split precision for Ay
static __device__ __forceinline__ void sweep(
    const char* smc, uint32_t rbase, const __half* gHh, const __half* gLh, int NC, bool full,
    float (*acc)[4], int i1, int i2, int i3, int lane, uint4* A0, uint4* A1)
{
    const uint4* gH = (const uint4*)gHh;
    const uint4* gL = (const uint4*)gLh;
    const uint32_t smb = smem_u32(smc) + rbase;
    const uint32_t bxor = (uint32_t)((lane & 6) << 3);
    const uint32_t brow = ((uint32_t)(lane & 7) + ((uint32_t)((lane >> 3) & 1)) * 8) * 64;
    const uint32_t bcol0 = (((uint32_t)(lane >> 4) * 16)) ^ bxor;
    const uint32_t bcol1 = (32u + (uint32_t)(lane >> 4) * 16) ^ bxor;

#pragma unroll
    for (int i = 0; i < 12; ++i)
#pragma unroll
        for (int j = 0; j < 4; ++j) acc[i][j] = 0.0f;

#pragma unroll 1
    for (int c = 0; c < NC; c += 2) {
#pragma unroll
        for (int half = 0; half < 2; ++half) {
            const uint4* Ar = half ? A1 : A0;
            const uint32_t co = (uint32_t)(c + half) << 10;
            uint32_t br[8], bi[8];
            ldmB4(br,     smb + XRH_R + co + brow + bcol0);
            ldmB4(br + 4, smb + XRH_R + co + brow + bcol1);
            ldmB4(bi,     smb + XIH_R + co + brow + bcol0);
            ldmB4(bi + 4, smb + XIH_R + co + brow + bcol1);
            // k3 = (Bi-Br)h * xr  (br live)
#pragma unroll
            for (int nt = 0; nt < 4; ++nt)
                mma16816(acc[8 + nt], (const uint32_t*)&Ar[2], &br[nt * 2]);
            if (full) {
#pragma unroll
                for (int nt = 0; nt < 4; ++nt)
                    mma16816(acc[8 + nt], (const uint32_t*)&Ar[5], &br[nt * 2]);
            }
            // k2 = (Br+Bi)h * xi
#pragma unroll
            for (int nt = 0; nt < 4; ++nt)
                mma16816(acc[4 + nt], (const uint32_t*)&Ar[1], &bi[nt * 2]);
            if (full) {
#pragma unroll
                for (int nt = 0; nt < 4; ++nt)
                    mma16816(acc[4 + nt], (const uint32_t*)&Ar[4], &bi[nt * 2]);
            }
            // xs = xr + xi in-place, then k1 = Br_h * xs (+ Br_l * xs on pass 0)
#pragma unroll
            for (int j = 0; j < 8; ++j) br[j] = hadd2u(br[j], bi[j]);
#pragma unroll
            for (int nt = 0; nt < 4; ++nt)
                mma16816(acc[nt], (const uint32_t*)&Ar[0], &br[nt * 2]);
            if (full) {
#pragma unroll
                for (int nt = 0; nt < 4; ++nt)
                    mma16816(acc[nt], (const uint32_t*)&Ar[3], &br[nt * 2]);
                // pass-0 only: Wh * x_lo for all three terms (full 3-term Ay)
                uint32_t brl[8], bil[8];
                ldmB4(brl,     smb + XRL_R + co + brow + bcol0);
                ldmB4(brl + 4, smb + XRL_R + co + brow + bcol1);
                ldmB4(bil,     smb + XIL_R + co + brow + bcol0);
                ldmB4(bil + 4, smb + XIL_R + co + brow + bcol1);
#pragma unroll
                for (int nt = 0; nt < 4; ++nt)
                    mma16816(acc[8 + nt], (const uint32_t*)&Ar[2], &brl[nt * 2]);
#pragma unroll
                for (int nt = 0; nt < 4; ++nt)
                    mma16816(acc[4 + nt], (const uint32_t*)&Ar[1], &bil[nt * 2]);
#pragma unroll
                for (int j = 0; j < 8; ++j) brl[j] = hadd2u(brl[j], bil[j]);
#pragma unroll
                for (int nt = 0; nt < 4; ++nt)
                    mma16816(acc[nt], (const uint32_t*)&Ar[0], &brl[nt * 2]);
            }
            // prefetch this buffer's next chunk (within pass)
            const int pf = c + half + 2;
            if (pf < NC) ldA(half ? A1 : A0, gH, gL, i1, i2, i3, pf, full);
        }
    }
}

// ---------------- main fused kernel ----------------
__global__ __launch_bounds__(THREADS, 1)
void lista_main(const float* __restrict__ y,
                const float* __restrict__ etas,
                const float* __restrict__ gammas,
                float* __restrict__ out) {
    extern __shared__ char smc[];
    const int tid = threadIdx.x, lane = tid & 31, wid = tid >> 5;
    const long b0 = (long)blockIdx.x * NB;

    // stage y into buffer 0: yr -> XRH/XRL, yi -> XIH/XIL
    const float2* y2 = (const float2*)y;
    for (int idx = tid; idx < NB * 128; idx += THREADS) {
        const int n = idx >> 7, q = idx & 127;
        const float2 v = y2[(b0 + n) * 128 + q];
        const uint32_t off = swz64(q, n * 2);
        __half hr = __float2half_rn(v.x);
        __half hi = __float2half_rn(v.y);
        *(__half*)(smc + XRH_R + off) = hr;
        *(__half*)(smc + XRL_R + off) = __float2half_rn(v.x - __half2float(hr));
        *(__half*)(smc + XIH_R + off) = hi;
        *(__half*)(smc + XIL_R + off) = __float2half_rn(v.y - __half2float(hi));
    }
    __syncthreads();

    // lane geometry
    const int eg = lane >> 2, ec = lane & 3;
    // warp-local Gauss mtiles: k1 = gmt wid, k2 = gmt 16+wid, k3 = gmt 32+wid
    const int i1 = wid * 32 + lane;
    const int i2 = (16 + wid) * 32 + lane;
    const int i3 = (32 + wid) * 32 + lane;

    float acc[12][4];
    uint4 A0[6], A1[6];
    ldA(A0, (const uint4*)g_WAH, (const uint4*)g_WAL, i1, i2, i3, 0, true);
    ldA(A1, (const uint4*)g_WAH, (const uint4*)g_WAL, i1, i2, i3, 1, true);

#pragma unroll 1
    for (int t = 0; t <= TT; ++t) {
        const bool full = (t == 0);
        const __half* WH = t ? g_WBH : g_WAH;
        const __half* WL = t ? g_WBL : g_WAL;
        const int NC = t ? 16 : 8;
        const uint32_t rb = (uint32_t)(t & 1) * BUFS;        // read buffer
        const uint32_t wb = (uint32_t)(1 - (t & 1)) * BUFS;  // write buffer

        sweep(smc, rb, WH, WL, NC, full, acc, i1, i2, i3, lane, A0, A1);

        // cross-pass A prefetch: hide next pass's cold-start LDGs under the epilogue
        if (t < TT) {
            ldA(A0, (const uint4*)g_WBH, (const uint4*)g_WBL, i1, i2, i3, 0, false);
            ldA(A1, (const uint4*)g_WBH, (const uint4*)g_WBL, i1, i2, i3, 1, false);
        }

        // warp-local combine + LISTA update (no barrier before: write buffer is inactive)
        const float g = gammas[t], e = etas[t];
#pragma unroll
        for (int nt = 0; nt < 4; ++nt)
#pragma unroll
            for (int rg = 0; rg < 2; ++rg) {
                const int m = 16 * wid + eg + rg * 8;
                const int n0 = nt * 8 + ec * 2;
                const uint32_t w = (uint32_t)m * 32 + scol(m, n0);
                const float k1a = acc[nt][rg * 2 + 0],     k1b = acc[nt][rg * 2 + 1];
                const float k2a = acc[4 + nt][rg * 2 + 0], k2b = acc[4 + nt][rg * 2 + 1];
                const float k3a = acc[8 + nt][rg * 2 + 0], k3b = acc[8 + nt][rg * 2 + 1];
                const float bre0 = k1a - k2a, bre1 = k1b - k2b;
                const float bim0 = k1a + k3a, bim1 = k1b + k3b;
                const uint32_t off = swz64(m, n0 * 2);
                float vre0, vre1, vim0, vim1;
                if (t == 0) {
                    *(float2*)(smc + AYR_OFF + w * 4) = make_float2(bre0, bre1);
                    *(float2*)(smc + AYI_OFF + w * 4) = make_float2(bim0, bim1);
                    vre0 = g * bre0; vre1 = g * bre1;
                    vim0 = g * bim0; vim1 = g * bim1;
                } else {
                    const float2 ar = *(const float2*)(smc + AYR_OFF + w * 4);
                    const float2 ai = *(const float2*)(smc + AYI_OFF + w * 4);
                    float2 fr  = __half22float2(*(const __half2*)(smc + rb + XRH_R + off));
                    float2 frl = __half22float2(*(const __half2*)(smc + rb + XRL_R + off));
                    float2 fi  = __half22float2(*(const __half2*)(smc + rb + XIH_R + off));
                    float2 fil = __half22float2(*(const __half2*)(smc + rb + XIL_R + off));
                    vre0 = fmaf(g, ar.x - bre0, fr.x + frl.x);
                    vre1 = fmaf(g, ar.y - bre1, fr.y + frl.y);
                    vim0 = fmaf(g, ai.x - bim0, fi.x + fil.x);
                    vim1 = fmaf(g, ai.y - bim1, fi.y + fil.y);
                }
                const float xr0 = copysignf(fmaxf(fabsf(vre0) - e, 0.0f), vre0);
                const float xr1 = copysignf(fmaxf(fabsf(vre1) - e, 0.0f), vre1);
                const float xi0 = copysignf(fmaxf(fabsf(vim0) - e, 0.0f), vim0);
                const float xi1 = copysignf(fmaxf(fabsf(vim1) - e, 0.0f), vim1);
                __half h0 = __float2half_rn(xr0), h1 = __float2half_rn(xr1);
                *(__half2*)(smc + wb + XRH_R + off) = __halves2half2(h0, h1);
                *(__half2*)(smc + wb + XRL_R + off) = __halves2half2(
                    __float2half_rn(xr0 - __half2float(h0)),
                    __float2half_rn(xr1 - __half2float(h1)));
                __half g0 = __float2half_rn(xi0), g1 = __float2half_rn(xi1);
                *(__half2*)(smc + wb + XIH_R + off) = __halves2half2(g0, g1);
                *(__half2*)(smc + wb + XIL_R + off) = __halves2half2(
                    __float2half_rn(xi0 - __half2float(g0)),
                    __float2half_rn(xi1 - __half2float(g1)));
            }
        __syncthreads();   // one barrier per pass: wb visible before next sweep reads it
    }

    // output: pass TT wrote buffer 1
    const char* xf = smc + BUFS;
    for (int idx = tid; idx < NB * 512; idx += THREADS) {
        const int n = idx >> 9, i = idx & 511, m = i >> 1, cc = i & 1;
        const uint32_t ph = cc ? XIH_R : XRH_R;
        const uint32_t pl = cc ? XIL_R : XRL_R;
        const uint32_t off = swz64(m, n * 2);
        const float v = __half2float(*(const __half*)(xf + ph + off))
                      + __half2float(*(const __half*)(xf + pl + off));
        out[(b0 + n) * 512 + i] = v;
    }
}

extern "C" void kernel_launch(void* const* d_in, const int* in_sizes, int n_in,
                              void* d_out, int out_size) {
    const float* y      = (const float*)d_in[0];
    const float* A      = (const float*)d_in[1];
    const float* B      = (const float*)d_in[2];
    const float* etas   = (const float*)d_in[3];
    const float* gammas = (const float*)d_in[4];
    float* out = (float*)d_out;

    prep_kernel<<<576, 512>>>(A, B);

    cudaFuncSetAttribute(lista_main, cudaFuncAttributeMaxDynamicSharedMemorySize, SMEM_TOTAL);
    lista_main<<<NCTA, THREADS, SMEM_TOTAL>>>(y, etas, gammas, out);
}